// round 10
// baseline (speedup 1.0000x reference)
#include <cuda_runtime.h>
#include <cstdint>

#define N_GAUSS 8192
#define GH 160
#define GW 160
#define GD 16
#define VOX 0.4f
#define VMINX (-32.0f)
#define VMINY (-32.0f)
#define VMINZ (-1.0f)
#define WCAP 1024

// Per-gaussian header: 3 x float4
//  [0] mu.x, mu.y, mu.z, c00
//  [1] 3sx, 3sy, 3sz, c11
//  [2] c22, 2*c01, c02, c12
__device__ float4 g_prec3[N_GAUSS * 3];
// Features pre-multiplied by opacity.
__device__ float g_featsc[N_GAUSS * 32];
// Packed integer voxel AABB: x = xmin|xmax<<8|ymin<<16|ymax<<24, y = zmin|zmax<<8
__device__ uint2 g_aabb[N_GAUSS];

__global__ void precompute_kernel(const float* __restrict__ means,
                                  const float* __restrict__ opac,
                                  const float* __restrict__ scales,
                                  const float* __restrict__ rots) {
    int i = blockIdx.x * blockDim.x + threadIdx.x;
    if (i >= N_GAUSS) return;

    float qw = rots[4*i+0], qx = rots[4*i+1], qy = rots[4*i+2], qz = rots[4*i+3];
    float invn = rsqrtf(qw*qw + qx*qx + qy*qy + qz*qz);
    qw *= invn; qx *= invn; qy *= invn; qz *= invn;

    float r00 = 1.f - 2.f*(qy*qy + qz*qz), r01 = 2.f*(qx*qy - qw*qz), r02 = 2.f*(qx*qz + qw*qy);
    float r10 = 2.f*(qx*qy + qw*qz), r11 = 1.f - 2.f*(qx*qx + qz*qz), r12 = 2.f*(qy*qz - qw*qx);
    float r20 = 2.f*(qx*qz - qw*qy), r21 = 2.f*(qy*qz + qw*qx), r22 = 1.f - 2.f*(qx*qx + qy*qy);

    float sx = scales[3*i+0], sy = scales[3*i+1], sz = scales[3*i+2];
    float ax = sx*sx, ay = sy*sy, az = sz*sz;
    float vx = 1.f/ax, vy = 1.f/ay, vz = 1.f/az;

    float s3x = 3.f * sqrtf(r00*r00*ax + r01*r01*ay + r02*r02*az);
    float s3y = 3.f * sqrtf(r10*r10*ax + r11*r11*ay + r12*r12*az);
    float s3z = 3.f * sqrtf(r20*r20*ax + r21*r21*ay + r22*r22*az);

    float c00 = r00*r00*vx + r01*r01*vy + r02*r02*vz;
    float c11 = r10*r10*vx + r11*r11*vy + r12*r12*vz;
    float c22 = r20*r20*vx + r21*r21*vy + r22*r22*vz;
    float c01 = r00*r10*vx + r01*r11*vy + r02*r12*vz;
    float c02 = r00*r20*vx + r01*r21*vy + r02*r22*vz;
    float c12 = r10*r20*vx + r11*r21*vy + r12*r22*vz;

    float mx = means[3*i+0], my = means[3*i+1], mz = means[3*i+2];

    g_prec3[3*i+0] = make_float4(mx, my, mz, c00);
    g_prec3[3*i+1] = make_float4(s3x, s3y, s3z, c11);
    g_prec3[3*i+2] = make_float4(c22, 2.f*c01, c02, c12);

    // Conservative integer voxel AABB (widened by 1 voxel each side).
    int x0 = (int)floorf((mx - s3x - VMINX) * 2.5f - 0.5f) - 1;
    int x1 = (int)floorf((mx + s3x - VMINX) * 2.5f - 0.5f) + 2;
    int y0 = (int)floorf((my - s3y - VMINY) * 2.5f - 0.5f) - 1;
    int y1 = (int)floorf((my + s3y - VMINY) * 2.5f - 0.5f) + 2;
    int z0 = (int)floorf((mz - s3z - VMINZ) * 2.5f - 0.5f) - 1;
    int z1 = (int)floorf((mz + s3z - VMINZ) * 2.5f - 0.5f) + 2;
    x0 = min(max(x0, 0), GH - 1); x1 = min(max(x1, 0), GH - 1);
    y0 = min(max(y0, 0), GW - 1); y1 = min(max(y1, 0), GW - 1);
    z0 = min(max(z0, 0), GD - 1); z1 = min(max(z1, 0), GD - 1);

    uint2 p;
    p.x = (unsigned)x0 | ((unsigned)x1 << 8) | ((unsigned)y0 << 16) | ((unsigned)y1 << 24);
    p.y = (unsigned)z0 | ((unsigned)z1 << 8);
    g_aabb[i] = p;
}

// Coalesced opacity-fold of features.
__global__ void featscale_kernel(const float* __restrict__ feats,
                                 const float* __restrict__ opac) {
    int j = blockIdx.x * blockDim.x + threadIdx.x;   // 0 .. N_GAUSS*32-1
    g_featsc[j] = opac[j >> 5] * feats[j];
}

// Tile = 8x8x4 voxels (256), 256 threads, 3 blocks/SM.
// Warp covers a 4x4x2 voxel cube; lane = (position, feature-half).
// Each thread: 2 z-adjacent voxels x 16 features = 32 accumulators.
__global__ void __launch_bounds__(256, 3) splat_kernel(float* __restrict__ out) {
    __shared__ unsigned short slist[N_GAUSS];
    __shared__ unsigned short wlist[8][WCAP];
    __shared__ int swarp[9];

    const int tid = threadIdx.x;
    const int tx0 = blockIdx.x * 8;
    const int ty0 = blockIdx.y * 8;
    const int tz0 = blockIdx.z * 4;
    const int lane = tid & 31, wid = tid >> 5;

    // ---- Level 1 cull: tile 8x8x4 ----
    const int base = tid * 32;
    int cnt = 0;
    #pragma unroll 8
    for (int k = 0; k < 32; k++) {
        uint2 p = g_aabb[base + k];
        int xmin = p.x & 255, xmax = (p.x >> 8) & 255;
        int ymin = (p.x >> 16) & 255, ymax = (p.x >> 24) & 255;
        int zmin = p.y & 255, zmax = (p.y >> 8) & 255;
        bool hit = (xmin <= tx0 + 7) & (xmax >= tx0) &
                   (ymin <= ty0 + 7) & (ymax >= ty0) &
                   (zmin <= tz0 + 3) & (zmax >= tz0);
        cnt += hit ? 1 : 0;
    }

    int inc = cnt;
    #pragma unroll
    for (int o = 1; o < 32; o <<= 1) {
        int y = __shfl_up_sync(0xffffffffu, inc, o);
        if (lane >= o) inc += y;
    }
    if (lane == 31) swarp[wid] = inc;
    __syncthreads();
    if (tid == 0) {
        int s = 0;
        #pragma unroll
        for (int w2 = 0; w2 < 8; w2++) { int t = swarp[w2]; swarp[w2] = s; s += t; }
        swarp[8] = s;
    }
    __syncthreads();
    int off = swarp[wid] + (inc - cnt);

    #pragma unroll 8
    for (int k = 0; k < 32; k++) {
        uint2 p = g_aabb[base + k];
        int xmin = p.x & 255, xmax = (p.x >> 8) & 255;
        int ymin = (p.x >> 16) & 255, ymax = (p.x >> 24) & 255;
        int zmin = p.y & 255, zmax = (p.y >> 8) & 255;
        bool hit = (xmin <= tx0 + 7) & (xmax >= tx0) &
                   (ymin <= ty0 + 7) & (ymax >= ty0) &
                   (zmin <= tz0 + 3) & (zmax >= tz0);
        if (hit) slist[off++] = (unsigned short)(base + k);
    }
    __syncthreads();
    const int nsurv = swarp[8];

    // ---- Warp-cube geometry: 8 warps arranged 2x2x2 over the 8x8x4 tile ----
    const int wx = (wid >> 2) & 1, wy = (wid >> 1) & 1, wz = wid & 1;
    const int wx0 = tx0 + wx * 4, wy0 = ty0 + wy * 4, wz0 = tz0 + wz * 2;
    // lane: bit0 = feature half, bits1-4 = position within 4x4 xy
    const int half = lane & 1;
    const int pos  = lane >> 1;
    const int ix = wx0 + (pos >> 2);
    const int iy = wy0 + (pos & 3);
    const float cx  = ((float)ix + 0.5f) * VOX + VMINX;
    const float cy  = ((float)iy + 0.5f) * VOX + VMINY;
    const float cz0 = ((float)wz0 + 0.5f) * VOX + VMINZ;
    const float cz1 = ((float)(wz0 + 1) + 0.5f) * VOX + VMINZ;

    float acc0[16], acc1[16];
    #pragma unroll
    for (int k = 0; k < 16; k++) { acc0[k] = 0.f; acc1[k] = 0.f; }

    const bool useWarpList = (nsurv <= WCAP);

    if (useWarpList) {
        // ---- Level 2 cull: warp re-culls slist against its 4x4x2 cube ----
        int wcnt = 0;
        for (int b = 0; b < nsurv; b += 32) {
            int j = b + lane;
            bool hit = false;
            int g = 0;
            if (j < nsurv) {
                g = slist[j];
                uint2 p = g_aabb[g];
                int xmin = p.x & 255, xmax = (p.x >> 8) & 255;
                int ymin = (p.x >> 16) & 255, ymax = (p.x >> 24) & 255;
                int zmin = p.y & 255, zmax = (p.y >> 8) & 255;
                hit = (xmin <= wx0 + 3) & (xmax >= wx0) &
                      (ymin <= wy0 + 3) & (ymax >= wy0) &
                      (zmin <= wz0 + 1) & (zmax >= wz0);
            }
            unsigned mask = __ballot_sync(0xffffffffu, hit);
            if (hit) wlist[wid][wcnt + __popc(mask & ((1u << lane) - 1u))] = (unsigned short)g;
            wcnt += __popc(mask);
        }
        __syncwarp();

        // ---- Dense branch-free eval over the warp list ----
        int gi = (wcnt > 0) ? wlist[wid][0] : 0;
        float4 pa = g_prec3[3*gi + 0];
        float4 pb = g_prec3[3*gi + 1];
        float4 pc = g_prec3[3*gi + 2];

        for (int j = 0; j < wcnt; j++) {
            const int gcur = gi;
            const float4 f0 = pa;
            const float4 f1 = pb;
            const float4 f2 = pc;
            {
                int jn = (j + 1 < wcnt) ? (j + 1) : j;
                int gn = wlist[wid][jn];
                pa = g_prec3[3*gn + 0];
                pb = g_prec3[3*gn + 1];
                pc = g_prec3[3*gn + 2];
                gi = gn;
            }

            float dx = cx - f0.x, dy = cy - f0.y;
            float dz0 = cz0 - f0.z, dz1 = cz1 - f0.z;
            bool mxy = (fabsf(dx) <= f1.x) & (fabsf(dy) <= f1.y);
            bool m0 = mxy & (fabsf(dz0) <= f1.z);
            bool m1 = mxy & (fabsf(dz1) <= f1.z);

            float txy = f0.w * dx * dx + f1.w * dy * dy + f2.y * dx * dy;
            float u   = f2.z * dx + f2.w * dy;
            float e0 = __expf(-0.5f * (txy + f2.x * dz0 * dz0 + 2.f * dz0 * u));
            float e1 = __expf(-0.5f * (txy + f2.x * dz1 * dz1 + 2.f * dz1 * u));
            float wgt0 = m0 ? e0 : 0.f;
            float wgt1 = m1 ? e1 : 0.f;

            const float4* fp = (const float4*)(g_featsc + (size_t)gcur * 32 + half * 16);
            #pragma unroll
            for (int k = 0; k < 4; k++) {
                float4 f = __ldg(fp + k);
                acc0[4*k+0] += wgt0 * f.x;
                acc0[4*k+1] += wgt0 * f.y;
                acc0[4*k+2] += wgt0 * f.z;
                acc0[4*k+3] += wgt0 * f.w;
                acc1[4*k+0] += wgt1 * f.x;
                acc1[4*k+1] += wgt1 * f.y;
                acc1[4*k+2] += wgt1 * f.z;
                acc1[4*k+3] += wgt1 * f.w;
            }
        }
    } else {
        // ---- Fallback (nsurv > WCAP): ballot-guarded loop over slist ----
        for (int j = 0; j < nsurv; j++) {
            const int gcur = slist[j];
            float4 f0 = g_prec3[3*gcur + 0];
            float4 f1 = g_prec3[3*gcur + 1];
            float dx = cx - f0.x, dy = cy - f0.y;
            float dz0 = cz0 - f0.z, dz1 = cz1 - f0.z;
            bool mxy = (fabsf(dx) <= f1.x) & (fabsf(dy) <= f1.y);
            bool m0 = mxy & (fabsf(dz0) <= f1.z);
            bool m1 = mxy & (fabsf(dz1) <= f1.z);
            if (__ballot_sync(0xffffffffu, m0 | m1)) {
                float wgt0 = 0.f, wgt1 = 0.f;
                if (m0 | m1) {
                    float4 f2 = g_prec3[3*gcur + 2];
                    float txy = f0.w * dx * dx + f1.w * dy * dy + f2.y * dx * dy;
                    float u   = f2.z * dx + f2.w * dy;
                    if (m0) wgt0 = __expf(-0.5f * (txy + f2.x * dz0 * dz0 + 2.f * dz0 * u));
                    if (m1) wgt1 = __expf(-0.5f * (txy + f2.x * dz1 * dz1 + 2.f * dz1 * u));
                }
                const float4* fp = (const float4*)(g_featsc + (size_t)gcur * 32 + half * 16);
                #pragma unroll
                for (int k = 0; k < 4; k++) {
                    float4 f = __ldg(fp + k);
                    acc0[4*k+0] += wgt0 * f.x;
                    acc0[4*k+1] += wgt0 * f.y;
                    acc0[4*k+2] += wgt0 * f.z;
                    acc0[4*k+3] += wgt0 * f.w;
                    acc1[4*k+0] += wgt1 * f.x;
                    acc1[4*k+1] += wgt1 * f.y;
                    acc1[4*k+2] += wgt1 * f.z;
                    acc1[4*k+3] += wgt1 * f.w;
                }
            }
        }
    }

    // ---- Write out: this thread owns features [half*16, half*16+16) of 2 voxels ----
    size_t o = ((((size_t)ix) * GW + (size_t)iy) * GD + (size_t)wz0) * 32 + half * 16;
    float4* op0 = (float4*)(out + o);
    float4* op1 = (float4*)(out + o + 32);
    #pragma unroll
    for (int k = 0; k < 4; k++)
        op0[k] = make_float4(acc0[4*k+0], acc0[4*k+1], acc0[4*k+2], acc0[4*k+3]);
    #pragma unroll
    for (int k = 0; k < 4; k++)
        op1[k] = make_float4(acc1[4*k+0], acc1[4*k+1], acc1[4*k+2], acc1[4*k+3]);
}

extern "C" void kernel_launch(void* const* d_in, const int* in_sizes, int n_in,
                              void* d_out, int out_size) {
    const float* means  = (const float*)d_in[0];
    const float* opac   = (const float*)d_in[1];
    const float* scales = (const float*)d_in[2];
    const float* rots   = (const float*)d_in[3];
    const float* feats  = (const float*)d_in[4];
    float* out = (float*)d_out;

    precompute_kernel<<<(N_GAUSS + 255) / 256, 256>>>(means, opac, scales, rots);
    featscale_kernel<<<(N_GAUSS * 32) / 256, 256>>>(feats, opac);
    splat_kernel<<<dim3(GH / 8, GW / 8, GD / 4), 256>>>(out);
}

// round 12
// speedup vs baseline: 1.2902x; 1.2902x over previous
#include <cuda_runtime.h>
#include <cstdint>

#define N_GAUSS 8192
#define GH 160
#define GW 160
#define GD 16
#define VOX 0.4f
#define VMINX (-32.0f)
#define VMINY (-32.0f)
#define VMINZ (-1.0f)
#define WCAP 1024

// Per-gaussian header: 3 x float4
//  [0] mu.x, mu.y, mu.z, c00
//  [1] 3sx, 3sy, 3sz, c11
//  [2] c22, 2*c01, c02, c12
__device__ float4 g_prec3[N_GAUSS * 3];
// Features pre-multiplied by opacity.
__device__ float g_featsc[N_GAUSS * 32];
// Packed integer voxel AABB: x = xmin|xmax<<8|ymin<<16|ymax<<24, y = zmin|zmax<<8
__device__ uint2 g_aabb[N_GAUSS];

__global__ void precompute_kernel(const float* __restrict__ means,
                                  const float* __restrict__ opac,
                                  const float* __restrict__ scales,
                                  const float* __restrict__ rots) {
    int i = blockIdx.x * blockDim.x + threadIdx.x;
    if (i >= N_GAUSS) return;

    float qw = rots[4*i+0], qx = rots[4*i+1], qy = rots[4*i+2], qz = rots[4*i+3];
    float invn = rsqrtf(qw*qw + qx*qx + qy*qy + qz*qz);
    qw *= invn; qx *= invn; qy *= invn; qz *= invn;

    float r00 = 1.f - 2.f*(qy*qy + qz*qz), r01 = 2.f*(qx*qy - qw*qz), r02 = 2.f*(qx*qz + qw*qy);
    float r10 = 2.f*(qx*qy + qw*qz), r11 = 1.f - 2.f*(qx*qx + qz*qz), r12 = 2.f*(qy*qz - qw*qx);
    float r20 = 2.f*(qx*qz - qw*qy), r21 = 2.f*(qy*qz + qw*qx), r22 = 1.f - 2.f*(qx*qx + qy*qy);

    float sx = scales[3*i+0], sy = scales[3*i+1], sz = scales[3*i+2];
    float ax = sx*sx, ay = sy*sy, az = sz*sz;
    float vx = 1.f/ax, vy = 1.f/ay, vz = 1.f/az;

    float s3x = 3.f * sqrtf(r00*r00*ax + r01*r01*ay + r02*r02*az);
    float s3y = 3.f * sqrtf(r10*r10*ax + r11*r11*ay + r12*r12*az);
    float s3z = 3.f * sqrtf(r20*r20*ax + r21*r21*ay + r22*r22*az);

    float c00 = r00*r00*vx + r01*r01*vy + r02*r02*vz;
    float c11 = r10*r10*vx + r11*r11*vy + r12*r12*vz;
    float c22 = r20*r20*vx + r21*r21*vy + r22*r22*vz;
    float c01 = r00*r10*vx + r01*r11*vy + r02*r12*vz;
    float c02 = r00*r20*vx + r01*r21*vy + r02*r22*vz;
    float c12 = r10*r20*vx + r11*r21*vy + r12*r22*vz;

    float mx = means[3*i+0], my = means[3*i+1], mz = means[3*i+2];

    g_prec3[3*i+0] = make_float4(mx, my, mz, c00);
    g_prec3[3*i+1] = make_float4(s3x, s3y, s3z, c11);
    g_prec3[3*i+2] = make_float4(c22, 2.f*c01, c02, c12);

    // Conservative integer voxel AABB (widened by 1 voxel each side).
    int x0 = (int)floorf((mx - s3x - VMINX) * 2.5f - 0.5f) - 1;
    int x1 = (int)floorf((mx + s3x - VMINX) * 2.5f - 0.5f) + 2;
    int y0 = (int)floorf((my - s3y - VMINY) * 2.5f - 0.5f) - 1;
    int y1 = (int)floorf((my + s3y - VMINY) * 2.5f - 0.5f) + 2;
    int z0 = (int)floorf((mz - s3z - VMINZ) * 2.5f - 0.5f) - 1;
    int z1 = (int)floorf((mz + s3z - VMINZ) * 2.5f - 0.5f) + 2;
    x0 = min(max(x0, 0), GH - 1); x1 = min(max(x1, 0), GH - 1);
    y0 = min(max(y0, 0), GW - 1); y1 = min(max(y1, 0), GW - 1);
    z0 = min(max(z0, 0), GD - 1); z1 = min(max(z1, 0), GD - 1);

    uint2 p;
    p.x = (unsigned)x0 | ((unsigned)x1 << 8) | ((unsigned)y0 << 16) | ((unsigned)y1 << 24);
    p.y = (unsigned)z0 | ((unsigned)z1 << 8);
    g_aabb[i] = p;
}

// Coalesced opacity-fold of features.
__global__ void featscale_kernel(const float* __restrict__ feats,
                                 const float* __restrict__ opac) {
    int j = blockIdx.x * blockDim.x + threadIdx.x;   // 0 .. N_GAUSS*32-1
    g_featsc[j] = opac[j >> 5] * feats[j];
}

// Tile = 8x8x8 voxels, 256 threads, 2 z-adjacent voxels per thread.
// Level 1: block cull. Level 2: per-warp cull vs warp's 4x4x4 cube.
// Dense eval processes TWO gaussians per iteration for ILP.
__global__ void __launch_bounds__(256, 2) splat_kernel(float* __restrict__ out) {
    __shared__ unsigned short slist[N_GAUSS];
    __shared__ unsigned short wlist[8][WCAP];
    __shared__ int swarp[9];

    const int tid = threadIdx.x;
    const int tx0 = blockIdx.x * 8;
    const int ty0 = blockIdx.y * 8;
    const int tz0 = blockIdx.z * 8;
    const int lane = tid & 31, wid = tid >> 5;

    // ---- Level 1 cull ----
    const int base = tid * 32;
    int cnt = 0;
    #pragma unroll 8
    for (int k = 0; k < 32; k++) {
        uint2 p = g_aabb[base + k];
        int xmin = p.x & 255, xmax = (p.x >> 8) & 255;
        int ymin = (p.x >> 16) & 255, ymax = (p.x >> 24) & 255;
        int zmin = p.y & 255, zmax = (p.y >> 8) & 255;
        bool hit = (xmin <= tx0 + 7) & (xmax >= tx0) &
                   (ymin <= ty0 + 7) & (ymax >= ty0) &
                   (zmin <= tz0 + 7) & (zmax >= tz0);
        cnt += hit ? 1 : 0;
    }

    int inc = cnt;
    #pragma unroll
    for (int o = 1; o < 32; o <<= 1) {
        int y = __shfl_up_sync(0xffffffffu, inc, o);
        if (lane >= o) inc += y;
    }
    if (lane == 31) swarp[wid] = inc;
    __syncthreads();
    if (tid == 0) {
        int s = 0;
        #pragma unroll
        for (int w2 = 0; w2 < 8; w2++) { int t = swarp[w2]; swarp[w2] = s; s += t; }
        swarp[8] = s;
    }
    __syncthreads();
    int off = swarp[wid] + (inc - cnt);

    #pragma unroll 8
    for (int k = 0; k < 32; k++) {
        uint2 p = g_aabb[base + k];
        int xmin = p.x & 255, xmax = (p.x >> 8) & 255;
        int ymin = (p.x >> 16) & 255, ymax = (p.x >> 24) & 255;
        int zmin = p.y & 255, zmax = (p.y >> 8) & 255;
        bool hit = (xmin <= tx0 + 7) & (xmax >= tx0) &
                   (ymin <= ty0 + 7) & (ymax >= ty0) &
                   (zmin <= tz0 + 7) & (zmax >= tz0);
        if (hit) slist[off++] = (unsigned short)(base + k);
    }
    __syncthreads();
    const int nsurv = swarp[8];

    // ---- Warp-cube geometry ----
    const int wx = wid >> 2, wy = (wid >> 1) & 1, wz = wid & 1;
    const int wx0 = tx0 + wx * 4, wy0 = ty0 + wy * 4, wz0 = tz0 + wz * 4;
    const int ix = wx0 + (lane >> 3);
    const int iy = wy0 + ((lane >> 1) & 3);
    const int izh = wz0 + (lane & 1) * 2;
    const float cx  = ((float)ix + 0.5f) * VOX + VMINX;
    const float cy  = ((float)iy + 0.5f) * VOX + VMINY;
    const float cz0 = ((float)izh + 0.5f) * VOX + VMINZ;
    const float cz1 = ((float)(izh + 1) + 0.5f) * VOX + VMINZ;

    float acc0[32], acc1[32];
    #pragma unroll
    for (int k = 0; k < 32; k++) { acc0[k] = 0.f; acc1[k] = 0.f; }

    const bool useWarpList = (nsurv <= WCAP);

    if (useWarpList) {
        // ---- Level 2 cull: warp re-culls slist against its 4x4x4 cube ----
        int wcnt = 0;
        for (int b = 0; b < nsurv; b += 32) {
            int j = b + lane;
            bool hit = false;
            int g = 0;
            if (j < nsurv) {
                g = slist[j];
                uint2 p = g_aabb[g];
                int xmin = p.x & 255, xmax = (p.x >> 8) & 255;
                int ymin = (p.x >> 16) & 255, ymax = (p.x >> 24) & 255;
                int zmin = p.y & 255, zmax = (p.y >> 8) & 255;
                hit = (xmin <= wx0 + 3) & (xmax >= wx0) &
                      (ymin <= wy0 + 3) & (ymax >= wy0) &
                      (zmin <= wz0 + 3) & (zmax >= wz0);
            }
            unsigned mask = __ballot_sync(0xffffffffu, hit);
            if (hit) wlist[wid][wcnt + __popc(mask & ((1u << lane) - 1u))] = (unsigned short)g;
            wcnt += __popc(mask);
        }
        __syncwarp();

        // ---- Dense eval, two gaussians per iteration ----
        const unsigned short* wl = wlist[wid];
        int j = 0;
        for (; j + 2 <= wcnt; j += 2) {
            // fused 32-bit load of two 16-bit indices (j even -> aligned)
            unsigned pairidx = *(const unsigned*)(wl + j);
            int ga = pairidx & 0xffffu;
            int gb = pairidx >> 16;

            float4 a0 = g_prec3[3*ga + 0];
            float4 a1 = g_prec3[3*ga + 1];
            float4 a2 = g_prec3[3*ga + 2];
            float4 b0 = g_prec3[3*gb + 0];
            float4 b1 = g_prec3[3*gb + 1];
            float4 b2 = g_prec3[3*gb + 2];

            // gaussian A weights
            float dxa = cx - a0.x, dya = cy - a0.y;
            float dza0 = cz0 - a0.z, dza1 = cz1 - a0.z;
            bool mxya = (fabsf(dxa) <= a1.x) & (fabsf(dya) <= a1.y);
            bool ma0 = mxya & (fabsf(dza0) <= a1.z);
            bool ma1 = mxya & (fabsf(dza1) <= a1.z);
            float txya = a0.w * dxa * dxa + a1.w * dya * dya + a2.y * dxa * dya;
            float ua   = a2.z * dxa + a2.w * dya;
            float ea0 = __expf(-0.5f * (txya + a2.x * dza0 * dza0 + 2.f * dza0 * ua));
            float ea1 = __expf(-0.5f * (txya + a2.x * dza1 * dza1 + 2.f * dza1 * ua));
            float wa0 = ma0 ? ea0 : 0.f;
            float wa1 = ma1 ? ea1 : 0.f;

            // gaussian B weights (independent chain)
            float dxb = cx - b0.x, dyb = cy - b0.y;
            float dzb0 = cz0 - b0.z, dzb1 = cz1 - b0.z;
            bool mxyb = (fabsf(dxb) <= b1.x) & (fabsf(dyb) <= b1.y);
            bool mb0 = mxyb & (fabsf(dzb0) <= b1.z);
            bool mb1 = mxyb & (fabsf(dzb1) <= b1.z);
            float txyb = b0.w * dxb * dxb + b1.w * dyb * dyb + b2.y * dxb * dyb;
            float ub   = b2.z * dxb + b2.w * dyb;
            float eb0 = __expf(-0.5f * (txyb + b2.x * dzb0 * dzb0 + 2.f * dzb0 * ub));
            float eb1 = __expf(-0.5f * (txyb + b2.x * dzb1 * dzb1 + 2.f * dzb1 * ub));
            float wb0 = mb0 ? eb0 : 0.f;
            float wb1 = mb1 ? eb1 : 0.f;

            const float4* fpa = (const float4*)(g_featsc + (size_t)ga * 32);
            const float4* fpb = (const float4*)(g_featsc + (size_t)gb * 32);
            #pragma unroll
            for (int k = 0; k < 8; k++) {
                float4 fa = __ldg(fpa + k);
                float4 fb = __ldg(fpb + k);
                acc0[4*k+0] += wa0 * fa.x;  acc0[4*k+0] += wb0 * fb.x;
                acc0[4*k+1] += wa0 * fa.y;  acc0[4*k+1] += wb0 * fb.y;
                acc0[4*k+2] += wa0 * fa.z;  acc0[4*k+2] += wb0 * fb.z;
                acc0[4*k+3] += wa0 * fa.w;  acc0[4*k+3] += wb0 * fb.w;
                acc1[4*k+0] += wa1 * fa.x;  acc1[4*k+0] += wb1 * fb.x;
                acc1[4*k+1] += wa1 * fa.y;  acc1[4*k+1] += wb1 * fb.y;
                acc1[4*k+2] += wa1 * fa.z;  acc1[4*k+2] += wb1 * fb.z;
                acc1[4*k+3] += wa1 * fa.w;  acc1[4*k+3] += wb1 * fb.w;
            }
        }
        // odd tail
        if (j < wcnt) {
            int ga = wl[j];
            float4 a0 = g_prec3[3*ga + 0];
            float4 a1 = g_prec3[3*ga + 1];
            float4 a2 = g_prec3[3*ga + 2];
            float dxa = cx - a0.x, dya = cy - a0.y;
            float dza0 = cz0 - a0.z, dza1 = cz1 - a0.z;
            bool mxya = (fabsf(dxa) <= a1.x) & (fabsf(dya) <= a1.y);
            bool ma0 = mxya & (fabsf(dza0) <= a1.z);
            bool ma1 = mxya & (fabsf(dza1) <= a1.z);
            float txya = a0.w * dxa * dxa + a1.w * dya * dya + a2.y * dxa * dya;
            float ua   = a2.z * dxa + a2.w * dya;
            float ea0 = __expf(-0.5f * (txya + a2.x * dza0 * dza0 + 2.f * dza0 * ua));
            float ea1 = __expf(-0.5f * (txya + a2.x * dza1 * dza1 + 2.f * dza1 * ua));
            float wa0 = ma0 ? ea0 : 0.f;
            float wa1 = ma1 ? ea1 : 0.f;
            const float4* fpa = (const float4*)(g_featsc + (size_t)ga * 32);
            #pragma unroll
            for (int k = 0; k < 8; k++) {
                float4 fa = __ldg(fpa + k);
                acc0[4*k+0] += wa0 * fa.x;
                acc0[4*k+1] += wa0 * fa.y;
                acc0[4*k+2] += wa0 * fa.z;
                acc0[4*k+3] += wa0 * fa.w;
                acc1[4*k+0] += wa1 * fa.x;
                acc1[4*k+1] += wa1 * fa.y;
                acc1[4*k+2] += wa1 * fa.z;
                acc1[4*k+3] += wa1 * fa.w;
            }
        }
    } else {
        // ---- Fallback (nsurv > WCAP): ballot-guarded loop over slist ----
        for (int j = 0; j < nsurv; j++) {
            const int gcur = slist[j];
            float4 f0 = g_prec3[3*gcur + 0];
            float4 f1 = g_prec3[3*gcur + 1];
            float dx = cx - f0.x, dy = cy - f0.y;
            float dz0 = cz0 - f0.z, dz1 = cz1 - f0.z;
            bool mxy = (fabsf(dx) <= f1.x) & (fabsf(dy) <= f1.y);
            bool m0 = mxy & (fabsf(dz0) <= f1.z);
            bool m1 = mxy & (fabsf(dz1) <= f1.z);
            if (__ballot_sync(0xffffffffu, m0 | m1)) {
                float wgt0 = 0.f, wgt1 = 0.f;
                if (m0 | m1) {
                    float4 f2 = g_prec3[3*gcur + 2];
                    float txy = f0.w * dx * dx + f1.w * dy * dy + f2.y * dx * dy;
                    float u   = f2.z * dx + f2.w * dy;
                    if (m0) wgt0 = __expf(-0.5f * (txy + f2.x * dz0 * dz0 + 2.f * dz0 * u));
                    if (m1) wgt1 = __expf(-0.5f * (txy + f2.x * dz1 * dz1 + 2.f * dz1 * u));
                }
                const float4* fp = (const float4*)(g_featsc + (size_t)gcur * 32);
                #pragma unroll
                for (int k = 0; k < 8; k++) {
                    float4 f = __ldg(fp + k);
                    acc0[4*k+0] += wgt0 * f.x;
                    acc0[4*k+1] += wgt0 * f.y;
                    acc0[4*k+2] += wgt0 * f.z;
                    acc0[4*k+3] += wgt0 * f.w;
                    acc1[4*k+0] += wgt1 * f.x;
                    acc1[4*k+1] += wgt1 * f.y;
                    acc1[4*k+2] += wgt1 * f.z;
                    acc1[4*k+3] += wgt1 * f.w;
                }
            }
        }
    }

    size_t o = ((((size_t)ix) * GW + (size_t)iy) * GD + (size_t)izh) * 32;
    float4* op = (float4*)(out + o);
    #pragma unroll
    for (int k = 0; k < 8; k++)
        op[k] = make_float4(acc0[4*k+0], acc0[4*k+1], acc0[4*k+2], acc0[4*k+3]);
    #pragma unroll
    for (int k = 0; k < 8; k++)
        op[8 + k] = make_float4(acc1[4*k+0], acc1[4*k+1], acc1[4*k+2], acc1[4*k+3]);
}

extern "C" void kernel_launch(void* const* d_in, const int* in_sizes, int n_in,
                              void* d_out, int out_size) {
    const float* means  = (const float*)d_in[0];
    const float* opac   = (const float*)d_in[1];
    const float* scales = (const float*)d_in[2];
    const float* rots   = (const float*)d_in[3];
    const float* feats  = (const float*)d_in[4];
    float* out = (float*)d_out;

    precompute_kernel<<<(N_GAUSS + 255) / 256, 256>>>(means, opac, scales, rots);
    featscale_kernel<<<(N_GAUSS * 32) / 256, 256>>>(feats, opac);
    splat_kernel<<<dim3(GH / 8, GW / 8, GD / 8), 256>>>(out);
}

// round 13
// speedup vs baseline: 1.6927x; 1.3120x over previous
#include <cuda_runtime.h>
#include <cstdint>

#define N_GAUSS 8192
#define GH 160
#define GW 160
#define GD 16
#define VOX 0.4f
#define VMINX (-32.0f)
#define VMINY (-32.0f)
#define VMINZ (-1.0f)
#define WCAP 1024

// Per-gaussian header: 3 x float4
//  [0] mu.x, mu.y, mu.z, c00
//  [1] 3sx, 3sy, 3sz, c11
//  [2] c22, 2*c01, c02, c12
__device__ float4 g_prec3[N_GAUSS * 3];
// Features pre-multiplied by opacity.
__device__ float g_featsc[N_GAUSS * 32];
// Packed integer voxel AABB: x = xmin|xmax<<8|ymin<<16|ymax<<24, y = zmin|zmax<<8
__device__ uint2 g_aabb[N_GAUSS];

__global__ void precompute_kernel(const float* __restrict__ means,
                                  const float* __restrict__ opac,
                                  const float* __restrict__ scales,
                                  const float* __restrict__ rots) {
    int i = blockIdx.x * blockDim.x + threadIdx.x;
    if (i >= N_GAUSS) return;

    float qw = rots[4*i+0], qx = rots[4*i+1], qy = rots[4*i+2], qz = rots[4*i+3];
    float invn = rsqrtf(qw*qw + qx*qx + qy*qy + qz*qz);
    qw *= invn; qx *= invn; qy *= invn; qz *= invn;

    float r00 = 1.f - 2.f*(qy*qy + qz*qz), r01 = 2.f*(qx*qy - qw*qz), r02 = 2.f*(qx*qz + qw*qy);
    float r10 = 2.f*(qx*qy + qw*qz), r11 = 1.f - 2.f*(qx*qx + qz*qz), r12 = 2.f*(qy*qz - qw*qx);
    float r20 = 2.f*(qx*qz - qw*qy), r21 = 2.f*(qy*qz + qw*qx), r22 = 1.f - 2.f*(qx*qx + qy*qy);

    float sx = scales[3*i+0], sy = scales[3*i+1], sz = scales[3*i+2];
    float ax = sx*sx, ay = sy*sy, az = sz*sz;
    float vx = 1.f/ax, vy = 1.f/ay, vz = 1.f/az;

    float s3x = 3.f * sqrtf(r00*r00*ax + r01*r01*ay + r02*r02*az);
    float s3y = 3.f * sqrtf(r10*r10*ax + r11*r11*ay + r12*r12*az);
    float s3z = 3.f * sqrtf(r20*r20*ax + r21*r21*ay + r22*r22*az);

    float c00 = r00*r00*vx + r01*r01*vy + r02*r02*vz;
    float c11 = r10*r10*vx + r11*r11*vy + r12*r12*vz;
    float c22 = r20*r20*vx + r21*r21*vy + r22*r22*vz;
    float c01 = r00*r10*vx + r01*r11*vy + r02*r12*vz;
    float c02 = r00*r20*vx + r01*r21*vy + r02*r22*vz;
    float c12 = r10*r20*vx + r11*r21*vy + r12*r22*vz;

    float mx = means[3*i+0], my = means[3*i+1], mz = means[3*i+2];

    g_prec3[3*i+0] = make_float4(mx, my, mz, c00);
    g_prec3[3*i+1] = make_float4(s3x, s3y, s3z, c11);
    g_prec3[3*i+2] = make_float4(c22, 2.f*c01, c02, c12);

    // Tight integer voxel AABB with epsilon margin (0.01 voxel ~= 100x the
    // worst-case fp32 rounding of the index mapping; the exact mask test in
    // the splat kernel decides the boundary, this box only needs to contain
    // every voxel that can pass it).
    int x0 = (int)ceilf((mx - s3x - VMINX) * 2.5f - 0.5f - 0.01f);
    int x1 = (int)floorf((mx + s3x - VMINX) * 2.5f - 0.5f + 0.01f);
    int y0 = (int)ceilf((my - s3y - VMINY) * 2.5f - 0.5f - 0.01f);
    int y1 = (int)floorf((my + s3y - VMINY) * 2.5f - 0.5f + 0.01f);
    int z0 = (int)ceilf((mz - s3z - VMINZ) * 2.5f - 0.5f - 0.01f);
    int z1 = (int)floorf((mz + s3z - VMINZ) * 2.5f - 0.5f + 0.01f);
    x0 = min(max(x0, 0), GH - 1); x1 = min(max(x1, 0), GH - 1);
    y0 = min(max(y0, 0), GW - 1); y1 = min(max(y1, 0), GW - 1);
    z0 = min(max(z0, 0), GD - 1); z1 = min(max(z1, 0), GD - 1);

    uint2 p;
    p.x = (unsigned)x0 | ((unsigned)x1 << 8) | ((unsigned)y0 << 16) | ((unsigned)y1 << 24);
    p.y = (unsigned)z0 | ((unsigned)z1 << 8);
    g_aabb[i] = p;
}

// Coalesced opacity-fold of features.
__global__ void featscale_kernel(const float* __restrict__ feats,
                                 const float* __restrict__ opac) {
    int j = blockIdx.x * blockDim.x + threadIdx.x;   // 0 .. N_GAUSS*32-1
    g_featsc[j] = opac[j >> 5] * feats[j];
}

// Tile = 8x8x8 voxels, 256 threads, 2 z-adjacent voxels per thread.
// Level 1: block cull. Level 2: per-warp cull vs warp's 4x4x4 cube.
// Dense eval processes TWO gaussians per iteration for ILP.
__global__ void __launch_bounds__(256, 2) splat_kernel(float* __restrict__ out) {
    __shared__ unsigned short slist[N_GAUSS];
    __shared__ unsigned short wlist[8][WCAP];
    __shared__ int swarp[9];

    const int tid = threadIdx.x;
    const int tx0 = blockIdx.x * 8;
    const int ty0 = blockIdx.y * 8;
    const int tz0 = blockIdx.z * 8;
    const int lane = tid & 31, wid = tid >> 5;

    // ---- Level 1 cull ----
    const int base = tid * 32;
    int cnt = 0;
    #pragma unroll 8
    for (int k = 0; k < 32; k++) {
        uint2 p = g_aabb[base + k];
        int xmin = p.x & 255, xmax = (p.x >> 8) & 255;
        int ymin = (p.x >> 16) & 255, ymax = (p.x >> 24) & 255;
        int zmin = p.y & 255, zmax = (p.y >> 8) & 255;
        bool hit = (xmin <= tx0 + 7) & (xmax >= tx0) &
                   (ymin <= ty0 + 7) & (ymax >= ty0) &
                   (zmin <= tz0 + 7) & (zmax >= tz0);
        cnt += hit ? 1 : 0;
    }

    int inc = cnt;
    #pragma unroll
    for (int o = 1; o < 32; o <<= 1) {
        int y = __shfl_up_sync(0xffffffffu, inc, o);
        if (lane >= o) inc += y;
    }
    if (lane == 31) swarp[wid] = inc;
    __syncthreads();
    if (tid == 0) {
        int s = 0;
        #pragma unroll
        for (int w2 = 0; w2 < 8; w2++) { int t = swarp[w2]; swarp[w2] = s; s += t; }
        swarp[8] = s;
    }
    __syncthreads();
    int off = swarp[wid] + (inc - cnt);

    #pragma unroll 8
    for (int k = 0; k < 32; k++) {
        uint2 p = g_aabb[base + k];
        int xmin = p.x & 255, xmax = (p.x >> 8) & 255;
        int ymin = (p.x >> 16) & 255, ymax = (p.x >> 24) & 255;
        int zmin = p.y & 255, zmax = (p.y >> 8) & 255;
        bool hit = (xmin <= tx0 + 7) & (xmax >= tx0) &
                   (ymin <= ty0 + 7) & (ymax >= ty0) &
                   (zmin <= tz0 + 7) & (zmax >= tz0);
        if (hit) slist[off++] = (unsigned short)(base + k);
    }
    __syncthreads();
    const int nsurv = swarp[8];

    // ---- Warp-cube geometry ----
    const int wx = wid >> 2, wy = (wid >> 1) & 1, wz = wid & 1;
    const int wx0 = tx0 + wx * 4, wy0 = ty0 + wy * 4, wz0 = tz0 + wz * 4;
    const int ix = wx0 + (lane >> 3);
    const int iy = wy0 + ((lane >> 1) & 3);
    const int izh = wz0 + (lane & 1) * 2;
    const float cx  = ((float)ix + 0.5f) * VOX + VMINX;
    const float cy  = ((float)iy + 0.5f) * VOX + VMINY;
    const float cz0 = ((float)izh + 0.5f) * VOX + VMINZ;
    const float cz1 = ((float)(izh + 1) + 0.5f) * VOX + VMINZ;

    float acc0[32], acc1[32];
    #pragma unroll
    for (int k = 0; k < 32; k++) { acc0[k] = 0.f; acc1[k] = 0.f; }

    const bool useWarpList = (nsurv <= WCAP);

    if (useWarpList) {
        // ---- Level 2 cull: warp re-culls slist against its 4x4x4 cube ----
        int wcnt = 0;
        for (int b = 0; b < nsurv; b += 32) {
            int j = b + lane;
            bool hit = false;
            int g = 0;
            if (j < nsurv) {
                g = slist[j];
                uint2 p = g_aabb[g];
                int xmin = p.x & 255, xmax = (p.x >> 8) & 255;
                int ymin = (p.x >> 16) & 255, ymax = (p.x >> 24) & 255;
                int zmin = p.y & 255, zmax = (p.y >> 8) & 255;
                hit = (xmin <= wx0 + 3) & (xmax >= wx0) &
                      (ymin <= wy0 + 3) & (ymax >= wy0) &
                      (zmin <= wz0 + 3) & (zmax >= wz0);
            }
            unsigned mask = __ballot_sync(0xffffffffu, hit);
            if (hit) wlist[wid][wcnt + __popc(mask & ((1u << lane) - 1u))] = (unsigned short)g;
            wcnt += __popc(mask);
        }
        __syncwarp();

        // ---- Dense eval, two gaussians per iteration ----
        const unsigned short* wl = wlist[wid];
        int j = 0;
        for (; j + 2 <= wcnt; j += 2) {
            // fused 32-bit load of two 16-bit indices (j even -> aligned)
            unsigned pairidx = *(const unsigned*)(wl + j);
            int ga = pairidx & 0xffffu;
            int gb = pairidx >> 16;

            float4 a0 = g_prec3[3*ga + 0];
            float4 a1 = g_prec3[3*ga + 1];
            float4 a2 = g_prec3[3*ga + 2];
            float4 b0 = g_prec3[3*gb + 0];
            float4 b1 = g_prec3[3*gb + 1];
            float4 b2 = g_prec3[3*gb + 2];

            // gaussian A weights
            float dxa = cx - a0.x, dya = cy - a0.y;
            float dza0 = cz0 - a0.z, dza1 = cz1 - a0.z;
            bool mxya = (fabsf(dxa) <= a1.x) & (fabsf(dya) <= a1.y);
            bool ma0 = mxya & (fabsf(dza0) <= a1.z);
            bool ma1 = mxya & (fabsf(dza1) <= a1.z);
            float txya = a0.w * dxa * dxa + a1.w * dya * dya + a2.y * dxa * dya;
            float ua   = a2.z * dxa + a2.w * dya;
            float ea0 = __expf(-0.5f * (txya + a2.x * dza0 * dza0 + 2.f * dza0 * ua));
            float ea1 = __expf(-0.5f * (txya + a2.x * dza1 * dza1 + 2.f * dza1 * ua));
            float wa0 = ma0 ? ea0 : 0.f;
            float wa1 = ma1 ? ea1 : 0.f;

            // gaussian B weights (independent chain)
            float dxb = cx - b0.x, dyb = cy - b0.y;
            float dzb0 = cz0 - b0.z, dzb1 = cz1 - b0.z;
            bool mxyb = (fabsf(dxb) <= b1.x) & (fabsf(dyb) <= b1.y);
            bool mb0 = mxyb & (fabsf(dzb0) <= b1.z);
            bool mb1 = mxyb & (fabsf(dzb1) <= b1.z);
            float txyb = b0.w * dxb * dxb + b1.w * dyb * dyb + b2.y * dxb * dyb;
            float ub   = b2.z * dxb + b2.w * dyb;
            float eb0 = __expf(-0.5f * (txyb + b2.x * dzb0 * dzb0 + 2.f * dzb0 * ub));
            float eb1 = __expf(-0.5f * (txyb + b2.x * dzb1 * dzb1 + 2.f * dzb1 * ub));
            float wb0 = mb0 ? eb0 : 0.f;
            float wb1 = mb1 ? eb1 : 0.f;

            const float4* fpa = (const float4*)(g_featsc + (size_t)ga * 32);
            const float4* fpb = (const float4*)(g_featsc + (size_t)gb * 32);
            #pragma unroll
            for (int k = 0; k < 8; k++) {
                float4 fa = __ldg(fpa + k);
                float4 fb = __ldg(fpb + k);
                acc0[4*k+0] += wa0 * fa.x;  acc0[4*k+0] += wb0 * fb.x;
                acc0[4*k+1] += wa0 * fa.y;  acc0[4*k+1] += wb0 * fb.y;
                acc0[4*k+2] += wa0 * fa.z;  acc0[4*k+2] += wb0 * fb.z;
                acc0[4*k+3] += wa0 * fa.w;  acc0[4*k+3] += wb0 * fb.w;
                acc1[4*k+0] += wa1 * fa.x;  acc1[4*k+0] += wb1 * fb.x;
                acc1[4*k+1] += wa1 * fa.y;  acc1[4*k+1] += wb1 * fb.y;
                acc1[4*k+2] += wa1 * fa.z;  acc1[4*k+2] += wb1 * fb.z;
                acc1[4*k+3] += wa1 * fa.w;  acc1[4*k+3] += wb1 * fb.w;
            }
        }
        // odd tail
        if (j < wcnt) {
            int ga = wl[j];
            float4 a0 = g_prec3[3*ga + 0];
            float4 a1 = g_prec3[3*ga + 1];
            float4 a2 = g_prec3[3*ga + 2];
            float dxa = cx - a0.x, dya = cy - a0.y;
            float dza0 = cz0 - a0.z, dza1 = cz1 - a0.z;
            bool mxya = (fabsf(dxa) <= a1.x) & (fabsf(dya) <= a1.y);
            bool ma0 = mxya & (fabsf(dza0) <= a1.z);
            bool ma1 = mxya & (fabsf(dza1) <= a1.z);
            float txya = a0.w * dxa * dxa + a1.w * dya * dya + a2.y * dxa * dya;
            float ua   = a2.z * dxa + a2.w * dya;
            float ea0 = __expf(-0.5f * (txya + a2.x * dza0 * dza0 + 2.f * dza0 * ua));
            float ea1 = __expf(-0.5f * (txya + a2.x * dza1 * dza1 + 2.f * dza1 * ua));
            float wa0 = ma0 ? ea0 : 0.f;
            float wa1 = ma1 ? ea1 : 0.f;
            const float4* fpa = (const float4*)(g_featsc + (size_t)ga * 32);
            #pragma unroll
            for (int k = 0; k < 8; k++) {
                float4 fa = __ldg(fpa + k);
                acc0[4*k+0] += wa0 * fa.x;
                acc0[4*k+1] += wa0 * fa.y;
                acc0[4*k+2] += wa0 * fa.z;
                acc0[4*k+3] += wa0 * fa.w;
                acc1[4*k+0] += wa1 * fa.x;
                acc1[4*k+1] += wa1 * fa.y;
                acc1[4*k+2] += wa1 * fa.z;
                acc1[4*k+3] += wa1 * fa.w;
            }
        }
    } else {
        // ---- Fallback (nsurv > WCAP): ballot-guarded loop over slist ----
        for (int j = 0; j < nsurv; j++) {
            const int gcur = slist[j];
            float4 f0 = g_prec3[3*gcur + 0];
            float4 f1 = g_prec3[3*gcur + 1];
            float dx = cx - f0.x, dy = cy - f0.y;
            float dz0 = cz0 - f0.z, dz1 = cz1 - f0.z;
            bool mxy = (fabsf(dx) <= f1.x) & (fabsf(dy) <= f1.y);
            bool m0 = mxy & (fabsf(dz0) <= f1.z);
            bool m1 = mxy & (fabsf(dz1) <= f1.z);
            if (__ballot_sync(0xffffffffu, m0 | m1)) {
                float wgt0 = 0.f, wgt1 = 0.f;
                if (m0 | m1) {
                    float4 f2 = g_prec3[3*gcur + 2];
                    float txy = f0.w * dx * dx + f1.w * dy * dy + f2.y * dx * dy;
                    float u   = f2.z * dx + f2.w * dy;
                    if (m0) wgt0 = __expf(-0.5f * (txy + f2.x * dz0 * dz0 + 2.f * dz0 * u));
                    if (m1) wgt1 = __expf(-0.5f * (txy + f2.x * dz1 * dz1 + 2.f * dz1 * u));
                }
                const float4* fp = (const float4*)(g_featsc + (size_t)gcur * 32);
                #pragma unroll
                for (int k = 0; k < 8; k++) {
                    float4 f = __ldg(fp + k);
                    acc0[4*k+0] += wgt0 * f.x;
                    acc0[4*k+1] += wgt0 * f.y;
                    acc0[4*k+2] += wgt0 * f.z;
                    acc0[4*k+3] += wgt0 * f.w;
                    acc1[4*k+0] += wgt1 * f.x;
                    acc1[4*k+1] += wgt1 * f.y;
                    acc1[4*k+2] += wgt1 * f.z;
                    acc1[4*k+3] += wgt1 * f.w;
                }
            }
        }
    }

    size_t o = ((((size_t)ix) * GW + (size_t)iy) * GD + (size_t)izh) * 32;
    float4* op = (float4*)(out + o);
    #pragma unroll
    for (int k = 0; k < 8; k++)
        op[k] = make_float4(acc0[4*k+0], acc0[4*k+1], acc0[4*k+2], acc0[4*k+3]);
    #pragma unroll
    for (int k = 0; k < 8; k++)
        op[8 + k] = make_float4(acc1[4*k+0], acc1[4*k+1], acc1[4*k+2], acc1[4*k+3]);
}

extern "C" void kernel_launch(void* const* d_in, const int* in_sizes, int n_in,
                              void* d_out, int out_size) {
    const float* means  = (const float*)d_in[0];
    const float* opac   = (const float*)d_in[1];
    const float* scales = (const float*)d_in[2];
    const float* rots   = (const float*)d_in[3];
    const float* feats  = (const float*)d_in[4];
    float* out = (float*)d_out;

    precompute_kernel<<<(N_GAUSS + 255) / 256, 256>>>(means, opac, scales, rots);
    featscale_kernel<<<(N_GAUSS * 32) / 256, 256>>>(feats, opac);
    splat_kernel<<<dim3(GH / 8, GW / 8, GD / 8), 256>>>(out);
}

// round 16
// speedup vs baseline: 2.2760x; 1.3446x over previous
#include <cuda_runtime.h>
#include <cstdint>

#define N_GAUSS 8192
#define GH 160
#define GW 160
#define GD 16
#define VOX 0.4f
#define VMINX (-32.0f)
#define VMINY (-32.0f)
#define VMINZ (-1.0f)
#define WCAP 1024

// Per-gaussian header: 3 x float4
//  [0] mu.x, mu.y, mu.z, c00
//  [1] 3sx, 3sy, 3sz, c11
//  [2] c22, 2*c01, c02, c12
__device__ float4 g_prec3[N_GAUSS * 3];
// Features pre-multiplied by opacity.
__device__ float g_featsc[N_GAUSS * 32];
// Packed integer voxel AABB: x = xmin|xmax<<8|ymin<<16|ymax<<24, y = zmin|zmax<<8
__device__ uint2 g_aabb[N_GAUSS];

// Fused precompute: blocks 0..31 build per-gaussian headers + AABBs,
// blocks 32..1055 do the coalesced opacity-fold of features.
__global__ void precompute_kernel(const float* __restrict__ means,
                                  const float* __restrict__ opac,
                                  const float* __restrict__ scales,
                                  const float* __restrict__ rots,
                                  const float* __restrict__ feats) {
    if (blockIdx.x >= 32) {
        int j = (blockIdx.x - 32) * 256 + threadIdx.x;   // 0 .. N_GAUSS*32-1
        g_featsc[j] = opac[j >> 5] * feats[j];
        return;
    }
    int i = blockIdx.x * 256 + threadIdx.x;

    float qw = rots[4*i+0], qx = rots[4*i+1], qy = rots[4*i+2], qz = rots[4*i+3];
    float invn = rsqrtf(qw*qw + qx*qx + qy*qy + qz*qz);
    qw *= invn; qx *= invn; qy *= invn; qz *= invn;

    float r00 = 1.f - 2.f*(qy*qy + qz*qz), r01 = 2.f*(qx*qy - qw*qz), r02 = 2.f*(qx*qz + qw*qy);
    float r10 = 2.f*(qx*qy + qw*qz), r11 = 1.f - 2.f*(qx*qx + qz*qz), r12 = 2.f*(qy*qz - qw*qx);
    float r20 = 2.f*(qx*qz - qw*qy), r21 = 2.f*(qy*qz + qw*qx), r22 = 1.f - 2.f*(qx*qx + qy*qy);

    float sx = scales[3*i+0], sy = scales[3*i+1], sz = scales[3*i+2];
    float ax = sx*sx, ay = sy*sy, az = sz*sz;
    float vx = 1.f/ax, vy = 1.f/ay, vz = 1.f/az;

    float s3x = 3.f * sqrtf(r00*r00*ax + r01*r01*ay + r02*r02*az);
    float s3y = 3.f * sqrtf(r10*r10*ax + r11*r11*ay + r12*r12*az);
    float s3z = 3.f * sqrtf(r20*r20*ax + r21*r21*ay + r22*r22*az);

    float c00 = r00*r00*vx + r01*r01*vy + r02*r02*vz;
    float c11 = r10*r10*vx + r11*r11*vy + r12*r12*vz;
    float c22 = r20*r20*vx + r21*r21*vy + r22*r22*vz;
    float c01 = r00*r10*vx + r01*r11*vy + r02*r12*vz;
    float c02 = r00*r20*vx + r01*r21*vy + r02*r22*vz;
    float c12 = r10*r20*vx + r11*r21*vy + r12*r22*vz;

    float mx = means[3*i+0], my = means[3*i+1], mz = means[3*i+2];

    g_prec3[3*i+0] = make_float4(mx, my, mz, c00);
    g_prec3[3*i+1] = make_float4(s3x, s3y, s3z, c11);
    g_prec3[3*i+2] = make_float4(c22, 2.f*c01, c02, c12);

    // Tight integer voxel AABB with epsilon margin (0.01 voxel ~= 100x the
    // worst-case fp32 rounding of the index mapping; the exact mask test in
    // the splat kernel decides the boundary, this box only needs to contain
    // every voxel that can pass it).
    int x0 = (int)ceilf((mx - s3x - VMINX) * 2.5f - 0.5f - 0.01f);
    int x1 = (int)floorf((mx + s3x - VMINX) * 2.5f - 0.5f + 0.01f);
    int y0 = (int)ceilf((my - s3y - VMINY) * 2.5f - 0.5f - 0.01f);
    int y1 = (int)floorf((my + s3y - VMINY) * 2.5f - 0.5f + 0.01f);
    int z0 = (int)ceilf((mz - s3z - VMINZ) * 2.5f - 0.5f - 0.01f);
    int z1 = (int)floorf((mz + s3z - VMINZ) * 2.5f - 0.5f + 0.01f);
    x0 = min(max(x0, 0), GH - 1); x1 = min(max(x1, 0), GH - 1);
    y0 = min(max(y0, 0), GW - 1); y1 = min(max(y1, 0), GW - 1);
    z0 = min(max(z0, 0), GD - 1); z1 = min(max(z1, 0), GD - 1);

    uint2 p;
    p.x = (unsigned)x0 | ((unsigned)x1 << 8) | ((unsigned)y0 << 16) | ((unsigned)y1 << 24);
    p.y = (unsigned)z0 | ((unsigned)z1 << 8);
    g_aabb[i] = p;
}

// Tile = 8x8x8 voxels, 256 threads, 2 z-adjacent voxels per thread.
// Level 1: block cull (single AABB pass, hit bitmask). Level 2: per-warp
// cull vs warp's 4x4x4 cube. Dense eval, two gaussians per iteration.
__global__ void __launch_bounds__(256, 2) splat_kernel(float* __restrict__ out) {
    __shared__ unsigned short slist[N_GAUSS];
    __shared__ unsigned short wlist[8][WCAP];
    __shared__ int swarp[9];

    const int tid = threadIdx.x;
    const int tx0 = blockIdx.x * 8;
    const int ty0 = blockIdx.y * 8;
    const int tz0 = blockIdx.z * 8;
    const int lane = tid & 31, wid = tid >> 5;

    // ---- Level 1 cull: single pass, record hits in a 32-bit mask ----
    const int base = tid * 32;
    unsigned hmask = 0;
    #pragma unroll 8
    for (int k = 0; k < 32; k++) {
        uint2 p = g_aabb[base + k];
        int xmin = p.x & 255, xmax = (p.x >> 8) & 255;
        int ymin = (p.x >> 16) & 255, ymax = (p.x >> 24) & 255;
        int zmin = p.y & 255, zmax = (p.y >> 8) & 255;
        bool hit = (xmin <= tx0 + 7) & (xmax >= tx0) &
                   (ymin <= ty0 + 7) & (ymax >= ty0) &
                   (zmin <= tz0 + 7) & (zmax >= tz0);
        if (hit) hmask |= (1u << k);
    }
    int cnt = __popc(hmask);

    int inc = cnt;
    #pragma unroll
    for (int o = 1; o < 32; o <<= 1) {
        int y = __shfl_up_sync(0xffffffffu, inc, o);
        if (lane >= o) inc += y;
    }
    if (lane == 31) swarp[wid] = inc;
    __syncthreads();
    if (tid == 0) {
        int s = 0;
        #pragma unroll
        for (int w2 = 0; w2 < 8; w2++) { int t = swarp[w2]; swarp[w2] = s; s += t; }
        swarp[8] = s;
    }
    __syncthreads();
    int off = swarp[wid] + (inc - cnt);

    // Emit from the mask (ascending k -> identical ordering to a re-test pass)
    unsigned em = hmask;
    while (em) {
        int k = __ffs(em) - 1;
        em &= em - 1;
        slist[off++] = (unsigned short)(base + k);
    }
    __syncthreads();
    const int nsurv = swarp[8];

    // ---- Warp-cube geometry ----
    const int wx = wid >> 2, wy = (wid >> 1) & 1, wz = wid & 1;
    const int wx0 = tx0 + wx * 4, wy0 = ty0 + wy * 4, wz0 = tz0 + wz * 4;
    const int ix = wx0 + (lane >> 3);
    const int iy = wy0 + ((lane >> 1) & 3);
    const int izh = wz0 + (lane & 1) * 2;
    const float cx  = ((float)ix + 0.5f) * VOX + VMINX;
    const float cy  = ((float)iy + 0.5f) * VOX + VMINY;
    const float cz0 = ((float)izh + 0.5f) * VOX + VMINZ;
    const float cz1 = ((float)(izh + 1) + 0.5f) * VOX + VMINZ;

    float acc0[32], acc1[32];
    #pragma unroll
    for (int k = 0; k < 32; k++) { acc0[k] = 0.f; acc1[k] = 0.f; }

    const bool useWarpList = (nsurv <= WCAP);

    if (useWarpList) {
        // ---- Level 2 cull: warp re-culls slist against its 4x4x4 cube ----
        int wcnt = 0;
        for (int b = 0; b < nsurv; b += 32) {
            int j = b + lane;
            bool hit = false;
            int g = 0;
            if (j < nsurv) {
                g = slist[j];
                uint2 p = g_aabb[g];
                int xmin = p.x & 255, xmax = (p.x >> 8) & 255;
                int ymin = (p.x >> 16) & 255, ymax = (p.x >> 24) & 255;
                int zmin = p.y & 255, zmax = (p.y >> 8) & 255;
                hit = (xmin <= wx0 + 3) & (xmax >= wx0) &
                      (ymin <= wy0 + 3) & (ymax >= wy0) &
                      (zmin <= wz0 + 3) & (zmax >= wz0);
            }
            unsigned mask = __ballot_sync(0xffffffffu, hit);
            if (hit) wlist[wid][wcnt + __popc(mask & ((1u << lane) - 1u))] = (unsigned short)g;
            wcnt += __popc(mask);
        }
        __syncwarp();

        // ---- Dense eval, two gaussians per iteration ----
        const unsigned short* wl = wlist[wid];
        int j = 0;
        for (; j + 2 <= wcnt; j += 2) {
            // fused 32-bit load of two 16-bit indices (j even -> aligned)
            unsigned pairidx = *(const unsigned*)(wl + j);
            int ga = pairidx & 0xffffu;
            int gb = pairidx >> 16;

            float4 a0 = g_prec3[3*ga + 0];
            float4 a1 = g_prec3[3*ga + 1];
            float4 a2 = g_prec3[3*ga + 2];
            float4 b0 = g_prec3[3*gb + 0];
            float4 b1 = g_prec3[3*gb + 1];
            float4 b2 = g_prec3[3*gb + 2];

            // gaussian A weights
            float dxa = cx - a0.x, dya = cy - a0.y;
            float dza0 = cz0 - a0.z, dza1 = cz1 - a0.z;
            bool mxya = (fabsf(dxa) <= a1.x) & (fabsf(dya) <= a1.y);
            bool ma0 = mxya & (fabsf(dza0) <= a1.z);
            bool ma1 = mxya & (fabsf(dza1) <= a1.z);
            float txya = a0.w * dxa * dxa + a1.w * dya * dya + a2.y * dxa * dya;
            float ua   = a2.z * dxa + a2.w * dya;
            float ea0 = __expf(-0.5f * (txya + a2.x * dza0 * dza0 + 2.f * dza0 * ua));
            float ea1 = __expf(-0.5f * (txya + a2.x * dza1 * dza1 + 2.f * dza1 * ua));
            float wa0 = ma0 ? ea0 : 0.f;
            float wa1 = ma1 ? ea1 : 0.f;

            // gaussian B weights (independent chain)
            float dxb = cx - b0.x, dyb = cy - b0.y;
            float dzb0 = cz0 - b0.z, dzb1 = cz1 - b0.z;
            bool mxyb = (fabsf(dxb) <= b1.x) & (fabsf(dyb) <= b1.y);
            bool mb0 = mxyb & (fabsf(dzb0) <= b1.z);
            bool mb1 = mxyb & (fabsf(dzb1) <= b1.z);
            float txyb = b0.w * dxb * dxb + b1.w * dyb * dyb + b2.y * dxb * dyb;
            float ub   = b2.z * dxb + b2.w * dyb;
            float eb0 = __expf(-0.5f * (txyb + b2.x * dzb0 * dzb0 + 2.f * dzb0 * ub));
            float eb1 = __expf(-0.5f * (txyb + b2.x * dzb1 * dzb1 + 2.f * dzb1 * ub));
            float wb0 = mb0 ? eb0 : 0.f;
            float wb1 = mb1 ? eb1 : 0.f;

            const float4* fpa = (const float4*)(g_featsc + (size_t)ga * 32);
            const float4* fpb = (const float4*)(g_featsc + (size_t)gb * 32);
            #pragma unroll
            for (int k = 0; k < 8; k++) {
                float4 fa = __ldg(fpa + k);
                float4 fb = __ldg(fpb + k);
                acc0[4*k+0] += wa0 * fa.x;  acc0[4*k+0] += wb0 * fb.x;
                acc0[4*k+1] += wa0 * fa.y;  acc0[4*k+1] += wb0 * fb.y;
                acc0[4*k+2] += wa0 * fa.z;  acc0[4*k+2] += wb0 * fb.z;
                acc0[4*k+3] += wa0 * fa.w;  acc0[4*k+3] += wb0 * fb.w;
                acc1[4*k+0] += wa1 * fa.x;  acc1[4*k+0] += wb1 * fb.x;
                acc1[4*k+1] += wa1 * fa.y;  acc1[4*k+1] += wb1 * fb.y;
                acc1[4*k+2] += wa1 * fa.z;  acc1[4*k+2] += wb1 * fb.z;
                acc1[4*k+3] += wa1 * fa.w;  acc1[4*k+3] += wb1 * fb.w;
            }
        }
        // odd tail
        if (j < wcnt) {
            int ga = wl[j];
            float4 a0 = g_prec3[3*ga + 0];
            float4 a1 = g_prec3[3*ga + 1];
            float4 a2 = g_prec3[3*ga + 2];
            float dxa = cx - a0.x, dya = cy - a0.y;
            float dza0 = cz0 - a0.z, dza1 = cz1 - a0.z;
            bool mxya = (fabsf(dxa) <= a1.x) & (fabsf(dya) <= a1.y);
            bool ma0 = mxya & (fabsf(dza0) <= a1.z);
            bool ma1 = mxya & (fabsf(dza1) <= a1.z);
            float txya = a0.w * dxa * dxa + a1.w * dya * dya + a2.y * dxa * dya;
            float ua   = a2.z * dxa + a2.w * dya;
            float ea0 = __expf(-0.5f * (txya + a2.x * dza0 * dza0 + 2.f * dza0 * ua));
            float ea1 = __expf(-0.5f * (txya + a2.x * dza1 * dza1 + 2.f * dza1 * ua));
            float wa0 = ma0 ? ea0 : 0.f;
            float wa1 = ma1 ? ea1 : 0.f;
            const float4* fpa = (const float4*)(g_featsc + (size_t)ga * 32);
            #pragma unroll
            for (int k = 0; k < 8; k++) {
                float4 fa = __ldg(fpa + k);
                acc0[4*k+0] += wa0 * fa.x;
                acc0[4*k+1] += wa0 * fa.y;
                acc0[4*k+2] += wa0 * fa.z;
                acc0[4*k+3] += wa0 * fa.w;
                acc1[4*k+0] += wa1 * fa.x;
                acc1[4*k+1] += wa1 * fa.y;
                acc1[4*k+2] += wa1 * fa.z;
                acc1[4*k+3] += wa1 * fa.w;
            }
        }
    } else {
        // ---- Fallback (nsurv > WCAP): ballot-guarded loop over slist ----
        for (int j = 0; j < nsurv; j++) {
            const int gcur = slist[j];
            float4 f0 = g_prec3[3*gcur + 0];
            float4 f1 = g_prec3[3*gcur + 1];
            float dx = cx - f0.x, dy = cy - f0.y;
            float dz0 = cz0 - f0.z, dz1 = cz1 - f0.z;
            bool mxy = (fabsf(dx) <= f1.x) & (fabsf(dy) <= f1.y);
            bool m0 = mxy & (fabsf(dz0) <= f1.z);
            bool m1 = mxy & (fabsf(dz1) <= f1.z);
            if (__ballot_sync(0xffffffffu, m0 | m1)) {
                float wgt0 = 0.f, wgt1 = 0.f;
                if (m0 | m1) {
                    float4 f2 = g_prec3[3*gcur + 2];
                    float txy = f0.w * dx * dx + f1.w * dy * dy + f2.y * dx * dy;
                    float u   = f2.z * dx + f2.w * dy;
                    if (m0) wgt0 = __expf(-0.5f * (txy + f2.x * dz0 * dz0 + 2.f * dz0 * u));
                    if (m1) wgt1 = __expf(-0.5f * (txy + f2.x * dz1 * dz1 + 2.f * dz1 * u));
                }
                const float4* fp = (const float4*)(g_featsc + (size_t)gcur * 32);
                #pragma unroll
                for (int k = 0; k < 8; k++) {
                    float4 f = __ldg(fp + k);
                    acc0[4*k+0] += wgt0 * f.x;
                    acc0[4*k+1] += wgt0 * f.y;
                    acc0[4*k+2] += wgt0 * f.z;
                    acc0[4*k+3] += wgt0 * f.w;
                    acc1[4*k+0] += wgt1 * f.x;
                    acc1[4*k+1] += wgt1 * f.y;
                    acc1[4*k+2] += wgt1 * f.z;
                    acc1[4*k+3] += wgt1 * f.w;
                }
            }
        }
    }

    size_t o = ((((size_t)ix) * GW + (size_t)iy) * GD + (size_t)izh) * 32;
    float4* op = (float4*)(out + o);
    #pragma unroll
    for (int k = 0; k < 8; k++)
        op[k] = make_float4(acc0[4*k+0], acc0[4*k+1], acc0[4*k+2], acc0[4*k+3]);
    #pragma unroll
    for (int k = 0; k < 8; k++)
        op[8 + k] = make_float4(acc1[4*k+0], acc1[4*k+1], acc1[4*k+2], acc1[4*k+3]);
}

extern "C" void kernel_launch(void* const* d_in, const int* in_sizes, int n_in,
                              void* d_out, int out_size) {
    const float* means  = (const float*)d_in[0];
    const float* opac   = (const float*)d_in[1];
    const float* scales = (const float*)d_in[2];
    const float* rots   = (const float*)d_in[3];
    const float* feats  = (const float*)d_in[4];
    float* out = (float*)d_out;

    precompute_kernel<<<32 + (N_GAUSS * 32) / 256, 256>>>(means, opac, scales, rots, feats);
    splat_kernel<<<dim3(GH / 8, GW / 8, GD / 8), 256>>>(out);
}